// round 6
// baseline (speedup 1.0000x reference)
#include <cuda_runtime.h>

// ---------------- Problem constants (fixed shapes per reference) ----------------
#define NN    100000          // nodes
#define NE    1600000         // edges
#define GMAX  64              // graphs
#define ODIM  32              // output feature dim

// ---------------- Scratch (static device globals: allocation-free) ----------------
__device__ int   g_is64;
__device__ int   g_src[NE];
__device__ int   g_dst[NE];
__device__ int   g_batch[NN];
__device__ int   g_deg[NN];
__device__ float g_dinv[NN];
__device__ int   g_rowptr[NN + 1];
__device__ int   g_cursor[NN];
__device__ int   g_col[NE];
__device__ float g_nrm[NE];
__device__ float g_h[(size_t)NN * 64];   // GEMM output
__device__ float g_a[(size_t)NN * 64];   // aggregation output
__device__ float g_sum[GMAX * ODIM];
__device__ float g_cnt[GMAX];

// ---------------- dtype sniff: int64 vs int32 edge_index ----------------
// Values are node ids < 100000 < 2^31, so if data is int64 every odd 32-bit
// word of the first 256 entries is zero. For int32 data the odd words are
// random node ids (P(all zero) ~ 0).
__global__ void k_detect(const unsigned* __restrict__ ew) {
    int lane = threadIdx.x;
    bool allz = true;
    for (int i = lane; i < 256; i += 32)
        if (ew[2 * i + 1] != 0u) allz = false;
    unsigned b = __ballot_sync(0xffffffffu, allz);
    if (lane == 0) g_is64 = (b == 0xffffffffu) ? 1 : 0;
}

__global__ void k_convert_edges(const void* __restrict__ eptr, int ne, int n) {
    int i = blockIdx.x * blockDim.x + threadIdx.x;
    if (i >= ne) return;
    int s, d;
    if (g_is64) {
        const long long* p = (const long long*)eptr;
        s = (int)p[i];
        d = (int)p[(long long)ne + i];
    } else {
        const int* p = (const int*)eptr;
        s = p[i];
        d = p[ne + i];
    }
    // crash-safety clamp
    s = min(max(s, 0), n - 1);
    d = min(max(d, 0), n - 1);
    g_src[i] = s;
    g_dst[i] = d;
}

__global__ void k_convert_batch(const void* __restrict__ bptr, int n) {
    int i = blockIdx.x * blockDim.x + threadIdx.x;
    if (i >= n) return;
    int g;
    if (g_is64) g = (int)((const long long*)bptr)[i];
    else        g = ((const int*)bptr)[i];
    g_batch[i] = min(max(g, 0), GMAX - 1);
}

// ---------------- init: deg = 1 (self loop), zero pooling accumulators ----------------
__global__ void k_init(int n) {
    int i = blockIdx.x * blockDim.x + threadIdx.x;
    if (i < n) g_deg[i] = 1;
    if (i < GMAX * ODIM) g_sum[i] = 0.f;
    if (i < GMAX) g_cnt[i] = 0.f;
}

__global__ void k_degree(int ne) {
    int i = blockIdx.x * blockDim.x + threadIdx.x;
    if (i < ne) atomicAdd(&g_deg[g_dst[i]], 1);
}

__global__ void k_dinv(int n) {
    int i = blockIdx.x * blockDim.x + threadIdx.x;
    if (i < n) g_dinv[i] = rsqrtf((float)g_deg[i]);   // deg >= 1 always
}

// ---------------- single-block exclusive scan of (deg-1) -> rowptr, cursor ----------------
__global__ void k_scan(int n, int ne) {
    __shared__ int ps[1024];
    int t = threadIdx.x;
    int chunk = (n + 1023) / 1024;
    int s = t * chunk;
    int e = min(s + chunk, n);
    int sum = 0;
    for (int i = s; i < e; i++) sum += g_deg[i] - 1;
    ps[t] = sum;
    __syncthreads();
    // Hillis-Steele inclusive scan
    for (int off = 1; off < 1024; off <<= 1) {
        int v = ps[t];
        int add = (t >= off) ? ps[t - off] : 0;
        __syncthreads();
        ps[t] = v + add;
        __syncthreads();
    }
    int run = (t == 0) ? 0 : ps[t - 1];
    for (int i = s; i < e; i++) {
        g_rowptr[i] = run;
        g_cursor[i] = run;
        run += g_deg[i] - 1;
    }
    if (t == 0) g_rowptr[n] = ne;
}

__global__ void k_fill(int ne) {
    int i = blockIdx.x * blockDim.x + threadIdx.x;
    if (i >= ne) return;
    int s = g_src[i];
    int d = g_dst[i];
    int p = atomicAdd(&g_cursor[d], 1);
    g_col[p] = s;
    g_nrm[p] = g_dinv[s] * g_dinv[d];
}

// ---------------- dense GEMM: out[n,M] = in[n,64] @ W[64,M] ----------------
// 64 rows per block, W staged in SMEM, X staged conflict-free (stride 65),
// 4x8 register micro-tile per thread.
template <int M>
__global__ void k_gemm(const float* __restrict__ in, const float* __restrict__ w, int n) {
    constexpr int CG = M / 8;          // col groups
    constexpr int NT = 16 * CG;        // threads (128 for M=64, 64 for M=32)
    __shared__ float ws[64 * M];
    __shared__ float xs[64 * 65];
    const float* x = in ? in : g_a;
    float* out = g_h;
    int tid = threadIdx.x;
    int rb = blockIdx.x * 64;

    // stage W (coalesced, linear)
    for (int i = tid; i < 64 * M / 4; i += NT)
        ((float4*)ws)[i] = ((const float4*)w)[i];

    // stage X: 64 rows x 64 cols, padded row stride 65
    for (int i = tid; i < 64 * 16; i += NT) {
        int row = i >> 4;
        int k4 = (i & 15) << 2;
        float4 v = make_float4(0.f, 0.f, 0.f, 0.f);
        if (rb + row < n) v = *(const float4*)&x[(size_t)(rb + row) * 64 + k4];
        float* xp = &xs[row * 65 + k4];
        xp[0] = v.x; xp[1] = v.y; xp[2] = v.z; xp[3] = v.w;
    }
    __syncthreads();

    int colg = tid % CG;
    int rowg = tid / CG;  // 0..15
    float acc[4][8];
#pragma unroll
    for (int i = 0; i < 4; i++)
#pragma unroll
        for (int j = 0; j < 8; j++) acc[i][j] = 0.f;

    const float* xp = &xs[rowg * 4 * 65];
    const float* wp = &ws[colg * 8];
#pragma unroll 4
    for (int k = 0; k < 64; k++) {
        float x0 = xp[k];
        float x1 = xp[65 + k];
        float x2 = xp[130 + k];
        float x3 = xp[195 + k];
        float4 wa = *(const float4*)&wp[k * M];
        float4 wb = *(const float4*)&wp[k * M + 4];
        float wv[8] = {wa.x, wa.y, wa.z, wa.w, wb.x, wb.y, wb.z, wb.w};
#pragma unroll
        for (int j = 0; j < 8; j++) {
            acc[0][j] += x0 * wv[j];
            acc[1][j] += x1 * wv[j];
            acc[2][j] += x2 * wv[j];
            acc[3][j] += x3 * wv[j];
        }
    }
#pragma unroll
    for (int i = 0; i < 4; i++) {
        int r = rb + rowg * 4 + i;
        if (r < n) {
            float* op = &out[(size_t)r * M + colg * 8];
            *(float4*)&op[0] = make_float4(acc[i][0], acc[i][1], acc[i][2], acc[i][3]);
            *(float4*)&op[4] = make_float4(acc[i][4], acc[i][5], acc[i][6], acc[i][7]);
        }
    }
}

// ---------------- sparse aggregation: one warp per node, lanes = features ----------------
// out[v] = dinv[v]^2 * h[v] + sum_{e in CSR(v)} nrm[e] * h[col[e]]  + bias  (opt relu)
template <int F>   // 64 or 32
__global__ void k_agg(const float* __restrict__ bias, int n, int relu) {
    int gw = (blockIdx.x * blockDim.x + threadIdx.x) >> 5;
    int lane = threadIdx.x & 31;
    if (gw >= n) return;
    int v = gw;
    const float* h = g_h;
    float dv = g_dinv[v];
    float a0, a1 = 0.f;
    if (F == 64) {
        float2 t = ((const float2*)h)[(size_t)v * 32 + lane];
        a0 = dv * dv * t.x;
        a1 = dv * dv * t.y;
    } else {
        a0 = dv * dv * h[(size_t)v * 32 + lane];
    }
    int beg = g_rowptr[v];
    int end = g_rowptr[v + 1];
    for (int base = beg; base < end; base += 32) {
        int idx = base + lane;
        int c = 0;
        float wv = 0.f;
        if (idx < end) { c = g_col[idx]; wv = g_nrm[idx]; }
        int m = end - base;
        if (m > 32) m = 32;
        int mr = (m + 7) & ~7;   // round to 8: invalid lanes carry wv=0
        for (int j0 = 0; j0 < mr; j0 += 8) {
#pragma unroll
            for (int jj = 0; jj < 8; jj++) {
                int j = j0 + jj;
                int s = __shfl_sync(0xffffffffu, c, j);
                float ww = __shfl_sync(0xffffffffu, wv, j);
                if (F == 64) {
                    float2 t = ((const float2*)h)[(size_t)s * 32 + lane];
                    a0 += ww * t.x;
                    a1 += ww * t.y;
                } else {
                    a0 += ww * h[(size_t)s * 32 + lane];
                }
            }
        }
    }
    if (F == 64) {
        float2 b = ((const float2*)bias)[lane];
        a0 += b.x; a1 += b.y;
        if (relu) { a0 = fmaxf(a0, 0.f); a1 = fmaxf(a1, 0.f); }
        ((float2*)g_a)[(size_t)v * 32 + lane] = make_float2(a0, a1);
    } else {
        a0 += bias[lane];
        if (relu) a0 = fmaxf(a0, 0.f);
        g_a[(size_t)v * 32 + lane] = a0;
    }
}

// ---------------- global mean pool: batch is SORTED -> warp-segmented sums ----------------
__global__ void k_pool(int n) {
    const int WN = 128;  // nodes per warp
    int warp = (blockIdx.x * blockDim.x + threadIdx.x) >> 5;
    int lane = threadIdx.x & 31;
    int s = warp * WN;
    if (s >= n) return;
    int e = min(s + WN, n);
    int cur = g_batch[s];
    float acc = 0.f, c = 0.f;
    for (int v = s; v < e; v++) {
        int g = g_batch[v];
        if (g != cur) {
            atomicAdd(&g_sum[cur * ODIM + lane], acc);
            if (lane == 0) atomicAdd(&g_cnt[cur], c);
            acc = 0.f; c = 0.f; cur = g;
        }
        acc += g_a[(size_t)v * ODIM + lane];
        c += 1.f;
    }
    atomicAdd(&g_sum[cur * ODIM + lane], acc);
    if (lane == 0) atomicAdd(&g_cnt[cur], c);
}

__global__ void k_final(float* __restrict__ out) {
    int i = blockIdx.x * blockDim.x + threadIdx.x;
    if (i < GMAX * ODIM) {
        float c = g_cnt[i / ODIM];
        out[i] = g_sum[i] / fmaxf(c, 1.f);
    }
}

// ---------------- launch ----------------
extern "C" void kernel_launch(void* const* d_in, const int* in_sizes, int n_in,
                              void* d_out, int out_size) {
    const float* x    = (const float*)d_in[0];
    const void*  eptr = d_in[1];
    const void*  bptr = d_in[2];
    int n  = in_sizes[2];          // nodes (batch length, dtype-independent)
    int ne = in_sizes[1] / 2;      // edges

    // locate weights (num_graphs scalar may or may not be a separate input)
    int wb = 3;
    for (int i = 3; i < n_in; i++) {
        if (in_sizes[i] == 64 * 64) { wb = i; break; }
    }
    const float* W1 = (const float*)d_in[wb + 0];
    const float* b1 = (const float*)d_in[wb + 1];
    const float* W2 = (const float*)d_in[wb + 2];
    const float* b2 = (const float*)d_in[wb + 3];
    const float* W3 = (const float*)d_in[wb + 4];
    const float* b3 = (const float*)d_in[wb + 5];
    float* out = (float*)d_out;

    int eb = (ne + 255) / 256;
    int nb = (n + 255) / 256;

    // graph preprocessing (every call: deterministic, graph-capturable)
    k_detect<<<1, 32>>>((const unsigned*)eptr);
    k_convert_edges<<<eb, 256>>>(eptr, ne, n);
    k_convert_batch<<<nb, 256>>>(bptr, n);
    k_init<<<nb, 256>>>(n);
    k_degree<<<eb, 256>>>(ne);
    k_dinv<<<nb, 256>>>(n);
    k_scan<<<1, 1024>>>(n, ne);
    k_fill<<<eb, 256>>>(ne);

    int gb = (n + 63) / 64;           // GEMM blocks
    int ab = (n + 7) / 8;             // agg blocks (256 thr = 8 warps = 8 nodes)

    // layer 1: GCNConv + ReLU
    k_gemm<64><<<gb, 128>>>(x, W1, n);
    k_agg<64><<<ab, 256>>>(b1, n, 1);
    // layer 2: GCNConv
    k_gemm<64><<<gb, 128>>>(nullptr, W2, n);
    k_agg<64><<<ab, 256>>>(b2, n, 0);
    // layer 3: GCNConv (64 -> 32)
    k_gemm<32><<<gb, 64>>>(nullptr, W3, n);
    k_agg<32><<<ab, 256>>>(b3, n, 0);

    // global mean pool
    int pw = (n + 127) / 128;                 // warps
    int pb = (pw * 32 + 255) / 256;           // blocks of 8 warps
    k_pool<<<pb, 256>>>(n);
    k_final<<<(GMAX * ODIM + 255) / 256, 256>>>(out);
}